// round 7
// baseline (speedup 1.0000x reference)
#include <cuda_runtime.h>
#include <cuda_fp16.h>
#include <math.h>
#include <stdint.h>

#define NN 50000
#define NE 800000
#define NGR 1024
#define CH 128
#define FIN 16
#define FE 3
#define NL 3
#define ET 64            // edges per tile
#define NETILES (NE / ET)
#define LN2F 0.69314718055994531f
#define L2EF 1.44269504088896341f
#define BN_EPS 1e-5f
#define SA 132   // A-operand smem row stride (floats), conflict-free
#define SB 136   // B-operand smem row stride (floats), conflict-free
#define SBU2 132 // edge B smem row stride in uint2: conflict-free
#define SM 136   // msg smem row stride (floats): conflict-free for STS.64 and column LDS

// ---------------- scratch ----------------
__device__ float g_h[NN * CH];
__device__ __half g_hin_h[NN * CH];
__device__ float g_agg[NN * CH];
__device__ float g_bnsum[CH];
__device__ float g_bnsq[CH];
__device__ float g_hg[NGR * CH];
__device__ float g_Wc[FIN * CH];
__device__ float g_bc[CH];
// sort scratch
__device__ int g_cnt[NN];
__device__ int g_pos[NN];
__device__ float4 g_sea[NE];   // sorted (ea0, ea1, ea2, env)
__device__ int g_ssrc[NE];
__device__ int g_sdst[NE];

__device__ __forceinline__ float ex2f(float x) {
    float r;
    asm("ex2.approx.f32 %0, %1;" : "=f"(r) : "f"(x));
    return r;
}
__device__ __forceinline__ float lg2f(float x) {
    float r;
    asm("lg2.approx.f32 %0, %1;" : "=f"(r) : "f"(x));
    return r;
}
__device__ __forceinline__ float sspf(float x) {
    float t = ex2f(-L2EF * fabsf(x));
    return fmaxf(x, 0.f) + LN2F * (lg2f(1.f + t) - 1.f);
}

__device__ __forceinline__ void red_add_v4(float* addr, float a, float b, float c, float d) {
    asm volatile("red.global.add.v4.f32 [%0], {%1,%2,%3,%4};"
                 :: "l"(addr), "f"(a), "f"(b), "f"(c), "f"(d) : "memory");
}
__device__ __forceinline__ void red_add_f32(float* addr, float v) {
    asm volatile("red.global.add.f32 [%0], %1;" :: "l"(addr), "f"(v) : "memory");
}

__device__ __forceinline__ uint32_t f2tf(float f) {
    uint32_t r;
    asm("cvt.rna.tf32.f32 %0, %1;" : "=r"(r) : "f"(f));
    return r;
}

__device__ __forceinline__ void mma8(float c[4], uint32_t a0, uint32_t a1, uint32_t a2, uint32_t a3,
                                     uint32_t b0, uint32_t b1) {
    asm volatile("mma.sync.aligned.m16n8k8.row.col.f32.tf32.tf32.f32 "
                 "{%0,%1,%2,%3},{%4,%5,%6,%7},{%8,%9},{%0,%1,%2,%3};"
                 : "+f"(c[0]), "+f"(c[1]), "+f"(c[2]), "+f"(c[3])
                 : "r"(a0), "r"(a1), "r"(a2), "r"(a3), "r"(b0), "r"(b1));
}

// ---------------- counting sort by dst ----------------
__global__ void hist_kernel(const int* __restrict__ dst) {
    int i = blockIdx.x * blockDim.x + threadIdx.x;
    if (i < NE) atomicAdd(&g_cnt[dst[i]], 1);
}

__global__ void scan_kernel() {
    __shared__ int sbuf[1024];
    __shared__ int carry;
    int t = threadIdx.x;
    if (t == 0) carry = 0;
    __syncthreads();
    for (int base = 0; base < NN; base += 1024) {
        int v = (base + t < NN) ? g_cnt[base + t] : 0;
        sbuf[t] = v;
        __syncthreads();
        for (int o = 1; o < 1024; o <<= 1) {
            int x = (t >= o) ? sbuf[t - o] : 0;
            __syncthreads();
            sbuf[t] += x;
            __syncthreads();
        }
        if (base + t < NN) g_pos[base + t] = carry + sbuf[t] - v;
        __syncthreads();
        if (t == 0) carry += sbuf[1023];
        __syncthreads();
    }
}

__global__ void materialize_kernel(const int* __restrict__ src, const int* __restrict__ dst,
                                   const float* __restrict__ ea, const float* __restrict__ ew) {
    int i = blockIdx.x * blockDim.x + threadIdx.x;
    if (i >= NE) return;
    int d = dst[i];
    int pos = atomicAdd(&g_pos[d], 1);
    float env = 0.5f * (cosf(ew[i] * 0.31415926535897931f) + 1.f);
    const float* eap = ea + (size_t)i * 3;
    g_sea[pos] = make_float4(eap[0], eap[1], eap[2], env);
    g_ssrc[pos] = src[i];
    g_sdst[pos] = d;
}

// ---------------- embed fold + embed ----------------
__global__ void prep_embed(const float* __restrict__ W_l1, const float* __restrict__ b_l1,
                           const float* __restrict__ W_l2, const float* __restrict__ b_l2) {
    int i = blockIdx.x * blockDim.x + threadIdx.x;
    if (i < FIN * CH) {
        int f = i >> 7, j = i & 127;
        float acc = 0.f;
        for (int k = 0; k < CH; k++) acc += W_l1[f * CH + k] * W_l2[k * CH + j];
        g_Wc[i] = acc;
    } else if (i < FIN * CH + CH) {
        int j = i - FIN * CH;
        float acc = b_l2[j];
        for (int k = 0; k < CH; k++) acc += b_l1[k] * W_l2[k * CH + j];
        g_bc[j] = acc;
    }
}

__global__ void embed_kernel(const float* __restrict__ x) {
    int idx = blockIdx.x * blockDim.x + threadIdx.x;
    if (idx >= NN * CH) return;
    int n = idx >> 7, j = idx & 127;
    const float* xr = x + n * FIN;
    float acc = g_bc[j];
#pragma unroll
    for (int f = 0; f < FIN; f++) acc += xr[f] * g_Wc[f * CH + j];
    g_h[idx] = acc;
}

// ---------------- persistent node GEMM ----------------
// MODE 1: g_hin_h = half(g_h @ W + b); also zero g_agg
// MODE 2: g_h    += ssp(g_agg @ W + b)   (+POOL: red to g_hg[batch])
#define NG_SMEM ((CH * SB + 64 * SA) * 4)

template <int MODE, int POOL>
__global__ __launch_bounds__(256, 2) void node_gemm(const float* __restrict__ W,
                                                    const float* __restrict__ b,
                                                    const int* __restrict__ batch) {
    extern __shared__ float sm[];
    uint32_t* WS = (uint32_t*)sm;
    float* XSf = sm + CH * SB;
    uint32_t* XS = (uint32_t*)XSf;
    const float* X = (MODE == 1) ? g_h : g_agg;

    int tid = threadIdx.x;
    for (int i = tid; i < CH * CH; i += 256)
        WS[(i >> 7) * SB + (i & 127)] = f2tf(W[i]);

    int lane = tid & 31, w = tid >> 5;
    int gid = lane >> 2, tig = lane & 3;
    int wm = w & 3, wn = w >> 2;
    int r0 = wm * 16 + gid;
    const int NT = (NN + 63) / 64;

    for (int tile = blockIdx.x; tile < NT; tile += gridDim.x) {
        int nb = tile * 64;
        __syncthreads();
        for (int i = tid; i < 64 * CH; i += 256) {
            int r = i >> 7, c = i & 127;
            int n = nb + r;
            XS[r * SA + c] = (n < NN) ? f2tf(X[(size_t)n * CH + c]) : 0u;
        }
        __syncthreads();

        float acc[8][4];
#pragma unroll
        for (int i = 0; i < 8; i++)
#pragma unroll
            for (int q = 0; q < 4; q++) acc[i][q] = 0.f;

#pragma unroll 4
        for (int k0 = 0; k0 < CH; k0 += 8) {
            int k1 = k0 + tig, k2 = k1 + 4;
            uint32_t a0 = XS[r0 * SA + k1];
            uint32_t a1 = XS[(r0 + 8) * SA + k1];
            uint32_t a2 = XS[r0 * SA + k2];
            uint32_t a3 = XS[(r0 + 8) * SA + k2];
#pragma unroll
            for (int ni = 0; ni < 8; ni++) {
                uint32_t b0 = WS[k1 * SB + wn * 64 + ni * 8 + gid];
                uint32_t b1 = WS[k2 * SB + wn * 64 + ni * 8 + gid];
                mma8(acc[ni], a0, a1, a2, a3, b0, b1);
            }
        }
        __syncthreads();
#pragma unroll
        for (int ni = 0; ni < 8; ni++) {
            int c = wn * 64 + ni * 8 + 2 * tig;
            *(float2*)(XSf + r0 * SA + c) = make_float2(acc[ni][0], acc[ni][1]);
            *(float2*)(XSf + (r0 + 8) * SA + c) = make_float2(acc[ni][2], acc[ni][3]);
        }
        __syncthreads();
#pragma unroll
        for (int it = 0; it < 8; it++) {
            int chunk = tid + it * 256;
            int r = chunk >> 5, cq = (chunk & 31) * 4;
            int n = nb + r;
            if (n >= NN) continue;
            float4 v = *(float4*)(XSf + r * SA + cq);
            float4 bb = *(const float4*)(b + cq);
            if (MODE == 2) {
                float* base = g_h + (size_t)n * CH + cq;
                float4 old = *(float4*)base;
                old.x += sspf(v.x + bb.x);
                old.y += sspf(v.y + bb.y);
                old.z += sspf(v.z + bb.z);
                old.w += sspf(v.w + bb.w);
                *(float4*)base = old;
                if (POOL) {
                    int g = batch[n];
                    red_add_v4(g_hg + (size_t)g * CH + cq, old.x, old.y, old.z, old.w);
                }
            } else {
                v.x += bb.x; v.y += bb.y; v.z += bb.z; v.w += bb.w;
                union { __half2 h[2]; uint2 u; } pk;
                pk.h[0] = __floats2half2_rn(v.x, v.y);
                pk.h[1] = __floats2half2_rn(v.z, v.w);
                *(uint2*)(g_hin_h + (size_t)n * CH + cq) = pk.u;
                *(float4*)(g_agg + (size_t)n * CH + cq) = make_float4(0.f, 0.f, 0.f, 0.f);
            }
        }
    }
}

// ---------------- BatchNorm ----------------
__global__ void bn_stats_kernel() {
    int c = threadIdx.x;
    float s = 0.f, q = 0.f;
    for (int n = blockIdx.x; n < NN; n += gridDim.x) {
        float v = g_h[n * CH + c];
        s += v; q += v * v;
    }
    atomicAdd(&g_bnsum[c], s);
    atomicAdd(&g_bnsq[c], q);
}

__global__ void bn_apply_kernel(const float* __restrict__ bn_g,
                                const float* __restrict__ bn_b) {
    int idx = blockIdx.x * blockDim.x + threadIdx.x;
    if (idx >= NN * CH) return;
    int c = idx & 127;
    float mu = g_bnsum[c] * (1.f / NN);
    float var = g_bnsq[c] * (1.f / NN) - mu * mu;
    g_h[idx] = (g_h[idx] - mu) * rsqrtf(var + BN_EPS) * bn_g[c] + bn_b[c];
}

// ---------------- persistent fused edge kernel (dst-sorted, segmented scatter) ----------------
// smem floats: WS2 16896 | W1p 512 | eaS 256 | be2S 128 | msgS 64*SM | src 64 + dst 64 ints
#define EDGE_SMEM ((16896 + 512 + 256 + 128 + 64 * SM + 128) * 4)

__global__ __launch_bounds__(128, 2) void edge_kernel(
    const float* __restrict__ We1, const float* __restrict__ be1,
    const float* __restrict__ We2, const float* __restrict__ be2) {
    extern __shared__ float sm[];
    uint2* WS2 = (uint2*)sm;                       // We2 tf32 pairs, stride SBU2
    float4* W1p = (float4*)(sm + 16896);           // 128: (We1_0, We1_1, We1_2, be1)
    float4* eaS = (float4*)(sm + 16896 + 512);     // 64: (ea0,ea1,ea2, env)
    float* be2S = sm + 16896 + 512 + 256;          // 128
    float* msgS = be2S + 128;                      // 64 x SM
    int* srcS = (int*)(msgS + 64 * SM);            // 64
    int* dstS = srcS + ET;                         // 64

    int tid = threadIdx.x;
    for (int i = tid; i < 16 * 4 * 128; i += 128) {
        int kg = i >> 9, rem = i & 511;
        int tg = rem >> 7, n = rem & 127;
        int k1 = kg * 8 + tg;
        WS2[(kg * 4 + tg) * SBU2 + n] =
            make_uint2(f2tf(We2[k1 * CH + n]), f2tf(We2[(k1 + 4) * CH + n]));
    }
    W1p[tid] = make_float4(We1[tid], We1[CH + tid], We1[2 * CH + tid], be1[tid]);
    be2S[tid] = be2[tid];
    __syncthreads();

    int lane = tid & 31, w = tid >> 5;
    int gid = lane >> 2, tig = lane & 3;
    int r0 = w * 16 + gid, r1 = r0 + 8;

    for (int tile = blockIdx.x; tile < NETILES; tile += gridDim.x) {
        int e0 = tile * ET;
        if (tid < ET) {
            eaS[tid] = g_sea[e0 + tid];
            srcS[tid] = g_ssrc[e0 + tid];
            dstS[tid] = g_sdst[e0 + tid];
        }
        __syncthreads();

        float4 eA = eaS[r0];
        float4 eB = eaS[r1];

        float acc[16][4];
#pragma unroll
        for (int i = 0; i < 16; i++)
#pragma unroll
            for (int q = 0; q < 4; q++) acc[i][q] = 0.f;

#pragma unroll 4
        for (int kg = 0; kg < 16; kg++) {
            int k1 = kg * 8 + tig;
            float4 wa = W1p[k1];
            float4 wb = W1p[k1 + 4];
            float uA1 = fmaf(eA.x, wa.x, fmaf(eA.y, wa.y, fmaf(eA.z, wa.z, wa.w)));
            float uB1 = fmaf(eB.x, wa.x, fmaf(eB.y, wa.y, fmaf(eB.z, wa.z, wa.w)));
            float uA2 = fmaf(eA.x, wb.x, fmaf(eA.y, wb.y, fmaf(eA.z, wb.z, wb.w)));
            float uB2 = fmaf(eB.x, wb.x, fmaf(eB.y, wb.y, fmaf(eB.z, wb.z, wb.w)));
            uint32_t a0 = f2tf(sspf(uA1));
            uint32_t a1 = f2tf(sspf(uB1));
            uint32_t a2 = f2tf(sspf(uA2));
            uint32_t a3 = f2tf(sspf(uB2));
            const uint2* bp = WS2 + (kg * 4 + tig) * SBU2 + gid;
#pragma unroll
            for (int ni = 0; ni < 16; ni++) {
                uint2 bb = bp[ni * 8];
                mma8(acc[ni], a0, a1, a2, a3, bb.x, bb.y);
            }
        }

        // write raw filter values to msg smem
#pragma unroll
        for (int ni = 0; ni < 16; ni++) {
            int c = ni * 8 + 2 * tig;
            *(float2*)(msgS + r0 * SM + c) = make_float2(acc[ni][0], acc[ni][1]);
            *(float2*)(msgS + r1 * SM + c) = make_float2(acc[ni][2], acc[ni][3]);
        }
        __syncthreads();

        // column phase: thread c walks sorted rows; combine equal-dst runs; 1 RED per run
        {
            int c = tid;
            float be2c = be2S[c];
            float accv = 0.f;
            int dprev = dstS[0];
#pragma unroll 8
            for (int r = 0; r < ET; r++) {
                float fv = msgS[r * SM + c];
                float4 e = eaS[r];
                int s = srcS[r];
                float h = __half2float(g_hin_h[(size_t)s * CH + c]);
                accv += (fv + be2c) * e.w * h;
                bool end = (r == ET - 1) || (dstS[r + 1] != dprev);
                if (end) {
                    red_add_f32(g_agg + (size_t)dprev * CH + c, accv);
                    accv = 0.f;
                    if (r < ET - 1) dprev = dstS[r + 1];
                }
            }
        }
        __syncthreads();
    }
}

// ---------------- readout MLP ----------------
__global__ void readout_kernel(const float* __restrict__ W_r1,
                               const float* __restrict__ b_r1,
                               const float* __restrict__ W_r2,
                               const float* __restrict__ b_r2,
                               float* __restrict__ out) {
    int g = blockIdx.x;
    int t = threadIdx.x;
    float acc = b_r1[t];
    for (int c = 0; c < CH; c++) acc += g_hg[g * CH + c] * W_r1[c * 32 + t];
    float r = sspf(acc);
    float p = r * W_r2[t];
#pragma unroll
    for (int o = 16; o; o >>= 1) p += __shfl_xor_sync(0xffffffffu, p, o);
    if (t == 0) out[g] = sspf(p + b_r2[0]);
}

// ---------------- launch ----------------
extern "C" void kernel_launch(void* const* d_in, const int* in_sizes, int n_in,
                              void* d_out, int out_size) {
    const float* x      = (const float*)d_in[0];
    const int*   eidx   = (const int*)d_in[1];
    const float* ew     = (const float*)d_in[2];
    const float* ea     = (const float*)d_in[3];
    const int*   batch  = (const int*)d_in[4];
    const float* W_l1   = (const float*)d_in[5];
    const float* b_l1   = (const float*)d_in[6];
    const float* W_l2   = (const float*)d_in[7];
    const float* b_l2   = (const float*)d_in[8];
    const float* bn_g   = (const float*)d_in[9];
    const float* bn_b   = (const float*)d_in[10];
    const float* Wi_in  = (const float*)d_in[11];
    const float* bi_in  = (const float*)d_in[12];
    const float* We1    = (const float*)d_in[13];
    const float* be1    = (const float*)d_in[14];
    const float* We2    = (const float*)d_in[15];
    const float* be2    = (const float*)d_in[16];
    const float* Wi_out = (const float*)d_in[17];
    const float* bi_out = (const float*)d_in[18];
    const float* W_r1   = (const float*)d_in[19];
    const float* b_r1   = (const float*)d_in[20];
    const float* W_r2   = (const float*)d_in[21];
    const float* b_r2   = (const float*)d_in[22];
    float* out = (float*)d_out;

    void *p_hg, *p_bns, *p_bnq, *p_cnt;
    cudaGetSymbolAddress(&p_hg, g_hg);
    cudaGetSymbolAddress(&p_bns, g_bnsum);
    cudaGetSymbolAddress(&p_bnq, g_bnsq);
    cudaGetSymbolAddress(&p_cnt, g_cnt);

    cudaFuncSetAttribute(node_gemm<1,0>, cudaFuncAttributeMaxDynamicSharedMemorySize, NG_SMEM);
    cudaFuncSetAttribute(node_gemm<2,0>, cudaFuncAttributeMaxDynamicSharedMemorySize, NG_SMEM);
    cudaFuncSetAttribute(node_gemm<2,1>, cudaFuncAttributeMaxDynamicSharedMemorySize, NG_SMEM);
    cudaFuncSetAttribute(edge_kernel, cudaFuncAttributeMaxDynamicSharedMemorySize, EDGE_SMEM);

    cudaMemsetAsync(p_bns, 0, CH * sizeof(float));
    cudaMemsetAsync(p_bnq, 0, CH * sizeof(float));
    cudaMemsetAsync(p_hg, 0, NGR * CH * sizeof(float));
    cudaMemsetAsync(p_cnt, 0, NN * sizeof(int));

    const int ng_grid = 2 * 148;
    const int e_grid = 2 * 148;

    // counting sort of edges by dst (+ env computation)
    hist_kernel<<<(NE + 255) / 256, 256>>>(eidx + NE);
    scan_kernel<<<1, 1024>>>();
    materialize_kernel<<<(NE + 255) / 256, 256>>>(eidx, eidx + NE, ea, ew);

    prep_embed<<<(FIN * CH + CH + 255) / 256, 256>>>(W_l1, b_l1, W_l2, b_l2);
    embed_kernel<<<(NN * CH + 255) / 256, 256>>>(x);

    bn_stats_kernel<<<256, 128>>>();
    bn_apply_kernel<<<(NN * CH + 255) / 256, 256>>>(bn_g, bn_b);

    for (int i = 0; i < NL; i++) {
        node_gemm<1,0><<<ng_grid, 256, NG_SMEM>>>(Wi_in + i * CH * CH, bi_in + i * CH, batch);
        edge_kernel<<<e_grid, 128, EDGE_SMEM>>>(We1 + i * FE * CH, be1 + i * CH,
                                                We2 + i * CH * CH, be2 + i * CH);
        if (i < NL - 1)
            node_gemm<2,0><<<ng_grid, 256, NG_SMEM>>>(Wi_out + i * CH * CH, bi_out + i * CH, batch);
        else
            node_gemm<2,1><<<ng_grid, 256, NG_SMEM>>>(Wi_out + i * CH * CH, bi_out + i * CH, batch);
    }

    readout_kernel<<<NGR, 32>>>(W_r1, b_r1, W_r2, b_r2, out);
}

// round 8
// speedup vs baseline: 2.2147x; 2.2147x over previous
#include <cuda_runtime.h>
#include <cuda_fp16.h>
#include <math.h>
#include <stdint.h>

#define NN 50000
#define NE 800000
#define NGR 1024
#define CH 128
#define FIN 16
#define FE 3
#define NL 3
#define ET 64            // edges per tile
#define NETILES (NE / ET)
#define LN2F 0.69314718055994531f
#define L2EF 1.44269504088896341f
#define BN_EPS 1e-5f
#define SA 132   // A-operand smem row stride (floats), conflict-free
#define SB 136   // B-operand smem row stride (floats), conflict-free
#define SBU2 132 // edge B smem row stride in uint2: conflict-free

// ---------------- scratch ----------------
__device__ float g_h[NN * CH];
__device__ __half g_hin_h[NN * CH];
__device__ __half g_aggh[NN * CH];
__device__ float g_env[NE];
__device__ float g_bnsum[CH];
__device__ float g_bnsq[CH];
__device__ float g_bnA[CH];
__device__ float g_bnB[CH];
__device__ float g_hg[NGR * CH];
__device__ float g_Wc[FIN * CH];
__device__ float g_bc[CH];

__device__ __forceinline__ float ex2f(float x) {
    float r;
    asm("ex2.approx.f32 %0, %1;" : "=f"(r) : "f"(x));
    return r;
}
__device__ __forceinline__ float lg2f(float x) {
    float r;
    asm("lg2.approx.f32 %0, %1;" : "=f"(r) : "f"(x));
    return r;
}
__device__ __forceinline__ float sspf(float x) {
    float t = ex2f(-L2EF * fabsf(x));
    return fmaxf(x, 0.f) + LN2F * (lg2f(1.f + t) - 1.f);
}

__device__ __forceinline__ void red_add_v4(float* addr, float a, float b, float c, float d) {
    asm volatile("red.global.add.v4.f32 [%0], {%1,%2,%3,%4};"
                 :: "l"(addr), "f"(a), "f"(b), "f"(c), "f"(d) : "memory");
}
__device__ __forceinline__ void red_add_h4(__half* addr, uint32_t p0, uint32_t p1) {
    asm volatile("red.global.add.noftz.v2.f16x2 [%0], {%1,%2};"
                 :: "l"(addr), "r"(p0), "r"(p1) : "memory");
}

__device__ __forceinline__ uint32_t f2tf(float f) {
    uint32_t r;
    asm("cvt.rna.tf32.f32 %0, %1;" : "=r"(r) : "f"(f));
    return r;
}
__device__ __forceinline__ uint32_t pack_h2(float a, float b) {
    __half2 h = __floats2half2_rn(a, b);
    return *(uint32_t*)&h;
}

__device__ __forceinline__ void mma8(float c[4], uint32_t a0, uint32_t a1, uint32_t a2, uint32_t a3,
                                     uint32_t b0, uint32_t b1) {
    asm volatile("mma.sync.aligned.m16n8k8.row.col.f32.tf32.tf32.f32 "
                 "{%0,%1,%2,%3},{%4,%5,%6,%7},{%8,%9},{%0,%1,%2,%3};"
                 : "+f"(c[0]), "+f"(c[1]), "+f"(c[2]), "+f"(c[3])
                 : "r"(a0), "r"(a1), "r"(a2), "r"(a3), "r"(b0), "r"(b1));
}

// ---------------- embed weight fold (warp per output) ----------------
__global__ void prep_embed(const float* __restrict__ W_l1, const float* __restrict__ b_l1,
                           const float* __restrict__ W_l2, const float* __restrict__ b_l2) {
    int wid = (blockIdx.x * blockDim.x + threadIdx.x) >> 5;
    int lane = threadIdx.x & 31;
    if (wid >= FIN * CH + CH / 1) { }
    if (wid < FIN * CH) {
        int f = wid >> 7, j = wid & 127;
        float p = 0.f;
#pragma unroll
        for (int i = 0; i < 4; i++) {
            int k = lane + 32 * i;
            p += W_l1[f * CH + k] * W_l2[k * CH + j];
        }
#pragma unroll
        for (int o = 16; o; o >>= 1) p += __shfl_xor_sync(0xffffffffu, p, o);
        if (lane == 0) g_Wc[wid] = p;
    } else if (wid < FIN * CH + CH) {
        int j = wid - FIN * CH;
        float p = 0.f;
#pragma unroll
        for (int i = 0; i < 4; i++) {
            int k = lane + 32 * i;
            p += b_l1[k] * W_l2[k * CH + j];
        }
#pragma unroll
        for (int o = 16; o; o >>= 1) p += __shfl_xor_sync(0xffffffffu, p, o);
        if (lane == 0) g_bc[j] = p + b_l2[j];
    }
}

// ---------------- fused embed + bn stats ----------------
__global__ __launch_bounds__(128) void embed_stats(const float* __restrict__ x) {
    __shared__ float WcS[FIN * CH];
    int tid = threadIdx.x;
    for (int i = tid; i < FIN * CH; i += 128) WcS[i] = g_Wc[i];
    __syncthreads();
    float bc = g_bc[tid];
    float s = 0.f, q = 0.f;
    for (int n = blockIdx.x; n < NN; n += gridDim.x) {
        const float* xr = x + (size_t)n * FIN;
        float acc = bc;
#pragma unroll
        for (int f = 0; f < FIN; f++) acc += xr[f] * WcS[f * CH + tid];
        g_h[(size_t)n * CH + tid] = acc;
        s += acc; q += acc * acc;
    }
    atomicAdd(&g_bnsum[tid], s);
    atomicAdd(&g_bnsq[tid], q);
}

__global__ void bn_coef(const float* __restrict__ bn_g, const float* __restrict__ bn_b) {
    int c = threadIdx.x;
    float mu = g_bnsum[c] * (1.f / NN);
    float var = g_bnsq[c] * (1.f / NN) - mu * mu;
    float a = rsqrtf(var + BN_EPS) * bn_g[c];
    g_bnA[c] = a;
    g_bnB[c] = bn_b[c] - mu * a;
}

// ---------------- envelope ----------------
__global__ void env_kernel(const float* __restrict__ ew) {
    int idx = blockIdx.x * blockDim.x + threadIdx.x;
    if (idx >= NE) return;
    g_env[idx] = 0.5f * (cosf(ew[idx] * 0.31415926535897931f) + 1.f);
}

// ---------------- persistent node GEMM ----------------
// MODE 1: g_hin_h = half(g_h @ W + b); zero g_aggh.  BNA: normalize g_h in-place during load.
// MODE 2: g_h += ssp(float(g_aggh) @ W + b)   (+POOL: red to g_hg[batch])
#define NG_SMEM ((CH * SB + 64 * SA + 256) * 4)

template <int MODE, int POOL, int BNA>
__global__ __launch_bounds__(256, 2) void node_gemm(const float* __restrict__ W,
                                                    const float* __restrict__ b,
                                                    const int* __restrict__ batch) {
    extern __shared__ float sm[];
    uint32_t* WS = (uint32_t*)sm;
    float* XSf = sm + CH * SB;
    uint32_t* XS = (uint32_t*)XSf;
    float* bnAS = sm + CH * SB + 64 * SA;
    float* bnBS = bnAS + 128;

    int tid = threadIdx.x;
    for (int i = tid; i < CH * CH; i += 256)
        WS[(i >> 7) * SB + (i & 127)] = f2tf(W[i]);
    if (BNA) {
        if (tid < 128) bnAS[tid] = g_bnA[tid];
        else bnBS[tid - 128] = g_bnB[tid - 128];
    }

    int lane = tid & 31, w = tid >> 5;
    int gid = lane >> 2, tig = lane & 3;
    int wm = w & 3, wn = w >> 2;
    int r0 = wm * 16 + gid;
    const int NT = (NN + 63) / 64;

    for (int tile = blockIdx.x; tile < NT; tile += gridDim.x) {
        int nb = tile * 64;
        __syncthreads();
        for (int i = tid; i < 64 * CH; i += 256) {
            int r = i >> 7, c = i & 127;
            int n = nb + r;
            float v = 0.f;
            if (n < NN) {
                if (MODE == 1) {
                    v = g_h[(size_t)n * CH + c];
                    if (BNA) {
                        v = v * bnAS[c] + bnBS[c];
                        g_h[(size_t)n * CH + c] = v;
                    }
                } else {
                    v = __half2float(g_aggh[(size_t)n * CH + c]);
                }
            }
            XS[r * SA + c] = f2tf(v);
        }
        __syncthreads();

        float acc[8][4];
#pragma unroll
        for (int i = 0; i < 8; i++)
#pragma unroll
            for (int q = 0; q < 4; q++) acc[i][q] = 0.f;

#pragma unroll 4
        for (int k0 = 0; k0 < CH; k0 += 8) {
            int k1 = k0 + tig, k2 = k1 + 4;
            uint32_t a0 = XS[r0 * SA + k1];
            uint32_t a1 = XS[(r0 + 8) * SA + k1];
            uint32_t a2 = XS[r0 * SA + k2];
            uint32_t a3 = XS[(r0 + 8) * SA + k2];
#pragma unroll
            for (int ni = 0; ni < 8; ni++) {
                uint32_t b0 = WS[k1 * SB + wn * 64 + ni * 8 + gid];
                uint32_t b1 = WS[k2 * SB + wn * 64 + ni * 8 + gid];
                mma8(acc[ni], a0, a1, a2, a3, b0, b1);
            }
        }
        __syncthreads();
#pragma unroll
        for (int ni = 0; ni < 8; ni++) {
            int c = wn * 64 + ni * 8 + 2 * tig;
            *(float2*)(XSf + r0 * SA + c) = make_float2(acc[ni][0], acc[ni][1]);
            *(float2*)(XSf + (r0 + 8) * SA + c) = make_float2(acc[ni][2], acc[ni][3]);
        }
        __syncthreads();
#pragma unroll
        for (int it = 0; it < 8; it++) {
            int chunk = tid + it * 256;
            int r = chunk >> 5, cq = (chunk & 31) * 4;
            int n = nb + r;
            if (n >= NN) continue;
            float4 v = *(float4*)(XSf + r * SA + cq);
            float4 bb = *(const float4*)(b + cq);
            if (MODE == 2) {
                float* base = g_h + (size_t)n * CH + cq;
                float4 old = *(float4*)base;
                old.x += sspf(v.x + bb.x);
                old.y += sspf(v.y + bb.y);
                old.z += sspf(v.z + bb.z);
                old.w += sspf(v.w + bb.w);
                *(float4*)base = old;
                if (POOL) {
                    int g = batch[n];
                    red_add_v4(g_hg + (size_t)g * CH + cq, old.x, old.y, old.z, old.w);
                }
            } else {
                v.x += bb.x; v.y += bb.y; v.z += bb.z; v.w += bb.w;
                union { __half2 h[2]; uint2 u; } pk;
                pk.h[0] = __floats2half2_rn(v.x, v.y);
                pk.h[1] = __floats2half2_rn(v.z, v.w);
                *(uint2*)(g_hin_h + (size_t)n * CH + cq) = pk.u;
                *(uint2*)(g_aggh + (size_t)n * CH + cq) = make_uint2(0u, 0u);
            }
        }
    }
}

// ---------------- persistent fused edge kernel ----------------
#define EDGE_SMEM ((16896 + 512 + 256 + 64 + 128 + 64 + 64) * 4)

__global__ __launch_bounds__(128, 3) void edge_kernel(
    const float* __restrict__ edge_attr,
    const int* __restrict__ src, const int* __restrict__ dst,
    const float* __restrict__ We1, const float* __restrict__ be1,
    const float* __restrict__ We2, const float* __restrict__ be2) {
    extern __shared__ float sm[];
    uint2* WS2 = (uint2*)sm;                       // We2 tf32 pairs, stride SBU2
    float4* W1p = (float4*)(sm + 16896);           // 128: (We1_0, We1_1, We1_2, be1)
    float4* eaS = (float4*)(sm + 16896 + 512);     // 64
    float* envS = sm + 16896 + 512 + 256;          // 64
    float* be2S = envS + ET;                       // 128
    int* srcS = (int*)(be2S + CH);                 // 64
    int* dstS = srcS + ET;                         // 64

    int tid = threadIdx.x;
    for (int i = tid; i < 16 * 4 * 128; i += 128) {
        int kg = i >> 9, rem = i & 511;
        int tg = rem >> 7, n = rem & 127;
        int k1 = kg * 8 + tg;
        WS2[(kg * 4 + tg) * SBU2 + n] =
            make_uint2(f2tf(We2[k1 * CH + n]), f2tf(We2[(k1 + 4) * CH + n]));
    }
    W1p[tid] = make_float4(We1[tid], We1[CH + tid], We1[2 * CH + tid], be1[tid]);
    be2S[tid] = be2[tid];
    __syncthreads();

    int lane = tid & 31, w = tid >> 5;
    int gid = lane >> 2, tig = lane & 3;
    int r0 = w * 16 + gid, r1 = r0 + 8;
    bool even = (tig & 1) == 0;
    int cb = (tig >> 1) * 4;

    for (int tile = blockIdx.x; tile < NETILES; tile += gridDim.x) {
        int e0 = tile * ET;
        if (tid < ET) {
            const float* eap = edge_attr + (size_t)(e0 + tid) * 3;
            eaS[tid] = make_float4(eap[0], eap[1], eap[2], 0.f);
            envS[tid] = g_env[e0 + tid];
            srcS[tid] = src[e0 + tid];
            dstS[tid] = dst[e0 + tid];
        }
        __syncthreads();

        float4 eA = eaS[r0];
        float4 eB = eaS[r1];

        float acc[16][4];
#pragma unroll
        for (int i = 0; i < 16; i++)
#pragma unroll
            for (int q = 0; q < 4; q++) acc[i][q] = 0.f;

#pragma unroll 4
        for (int kg = 0; kg < 16; kg++) {
            int k1 = kg * 8 + tig;
            float4 wa = W1p[k1];
            float4 wb = W1p[k1 + 4];
            float uA1 = fmaf(eA.x, wa.x, fmaf(eA.y, wa.y, fmaf(eA.z, wa.z, wa.w)));
            float uB1 = fmaf(eB.x, wa.x, fmaf(eB.y, wa.y, fmaf(eB.z, wa.z, wa.w)));
            float uA2 = fmaf(eA.x, wb.x, fmaf(eA.y, wb.y, fmaf(eA.z, wb.z, wb.w)));
            float uB2 = fmaf(eB.x, wb.x, fmaf(eB.y, wb.y, fmaf(eB.z, wb.z, wb.w)));
            uint32_t a0 = f2tf(sspf(uA1));
            uint32_t a1 = f2tf(sspf(uB1));
            uint32_t a2 = f2tf(sspf(uA2));
            uint32_t a3 = f2tf(sspf(uB2));
            const uint2* bp = WS2 + (kg * 4 + tig) * SBU2 + gid;
#pragma unroll
            for (int ni = 0; ni < 16; ni++) {
                uint2 bb = bp[ni * 8];
                mma8(acc[ni], a0, a1, a2, a3, bb.x, bb.y);
            }
        }

        // epilogue: pair lanes -> 4 cols, gather fp16 hin, modulate, fp16x2 RED scatter
        int rr = even ? r0 : r1;
        int s = srcS[rr], d = dstS[rr];
        float ev = envS[rr];
        const __half* hrow = g_hin_h + (size_t)s * CH;
        __half* arow = g_aggh + (size_t)d * CH;
#pragma unroll
        for (int ni = 0; ni < 16; ni++) {
            float sA = even ? acc[ni][2] : acc[ni][0];
            float rA = __shfl_xor_sync(0xffffffffu, sA, 1);
            float sB = even ? acc[ni][3] : acc[ni][1];
            float rB = __shfl_xor_sync(0xffffffffu, sB, 1);
            float fx, fy, fz, fw;
            if (even) { fx = acc[ni][0]; fy = acc[ni][1]; fz = rA; fw = rB; }
            else      { fx = rA; fy = rB; fz = acc[ni][2]; fw = acc[ni][3]; }
            int c = cb + ni * 8;
            uint2 hp = *(const uint2*)(hrow + c);
            float2 h01 = __half22float2(*(__half2*)&hp.x);
            float2 h23 = __half22float2(*(__half2*)&hp.y);
            float4 bb = *(const float4*)(be2S + c);
            uint32_t p0 = pack_h2(h01.x * (fx + bb.x) * ev, h01.y * (fy + bb.y) * ev);
            uint32_t p1 = pack_h2(h23.x * (fz + bb.z) * ev, h23.y * (fw + bb.w) * ev);
            red_add_h4(arow + c, p0, p1);
        }
        __syncthreads();
    }
}

// ---------------- readout MLP ----------------
__global__ void readout_kernel(const float* __restrict__ W_r1,
                               const float* __restrict__ b_r1,
                               const float* __restrict__ W_r2,
                               const float* __restrict__ b_r2,
                               float* __restrict__ out) {
    int g = blockIdx.x;
    int t = threadIdx.x;
    float acc = b_r1[t];
    for (int c = 0; c < CH; c++) acc += g_hg[g * CH + c] * W_r1[c * 32 + t];
    float r = sspf(acc);
    float p = r * W_r2[t];
#pragma unroll
    for (int o = 16; o; o >>= 1) p += __shfl_xor_sync(0xffffffffu, p, o);
    if (t == 0) out[g] = sspf(p + b_r2[0]);
}

// ---------------- launch ----------------
extern "C" void kernel_launch(void* const* d_in, const int* in_sizes, int n_in,
                              void* d_out, int out_size) {
    const float* x      = (const float*)d_in[0];
    const int*   eidx   = (const int*)d_in[1];
    const float* ew     = (const float*)d_in[2];
    const float* ea     = (const float*)d_in[3];
    const int*   batch  = (const int*)d_in[4];
    const float* W_l1   = (const float*)d_in[5];
    const float* b_l1   = (const float*)d_in[6];
    const float* W_l2   = (const float*)d_in[7];
    const float* b_l2   = (const float*)d_in[8];
    const float* bn_g   = (const float*)d_in[9];
    const float* bn_b   = (const float*)d_in[10];
    const float* Wi_in  = (const float*)d_in[11];
    const float* bi_in  = (const float*)d_in[12];
    const float* We1    = (const float*)d_in[13];
    const float* be1    = (const float*)d_in[14];
    const float* We2    = (const float*)d_in[15];
    const float* be2    = (const float*)d_in[16];
    const float* Wi_out = (const float*)d_in[17];
    const float* bi_out = (const float*)d_in[18];
    const float* W_r1   = (const float*)d_in[19];
    const float* b_r1   = (const float*)d_in[20];
    const float* W_r2   = (const float*)d_in[21];
    const float* b_r2   = (const float*)d_in[22];
    float* out = (float*)d_out;

    void *p_hg, *p_bns, *p_bnq;
    cudaGetSymbolAddress(&p_hg, g_hg);
    cudaGetSymbolAddress(&p_bns, g_bnsum);
    cudaGetSymbolAddress(&p_bnq, g_bnsq);

    cudaFuncSetAttribute(node_gemm<1,0,1>, cudaFuncAttributeMaxDynamicSharedMemorySize, NG_SMEM);
    cudaFuncSetAttribute(node_gemm<1,0,0>, cudaFuncAttributeMaxDynamicSharedMemorySize, NG_SMEM);
    cudaFuncSetAttribute(node_gemm<2,0,0>, cudaFuncAttributeMaxDynamicSharedMemorySize, NG_SMEM);
    cudaFuncSetAttribute(node_gemm<2,1,0>, cudaFuncAttributeMaxDynamicSharedMemorySize, NG_SMEM);
    cudaFuncSetAttribute(edge_kernel, cudaFuncAttributeMaxDynamicSharedMemorySize, EDGE_SMEM);

    cudaMemsetAsync(p_bns, 0, CH * sizeof(float));
    cudaMemsetAsync(p_bnq, 0, CH * sizeof(float));
    cudaMemsetAsync(p_hg, 0, NGR * CH * sizeof(float));

    const int ng_grid = 2 * 148;
    const int e_grid = 3 * 148;

    prep_embed<<<(FIN * CH + CH) * 32 / 256, 256>>>(W_l1, b_l1, W_l2, b_l2);
    embed_stats<<<2 * 148, 128>>>(x);
    bn_coef<<<1, 128>>>(bn_g, bn_b);
    env_kernel<<<(NE + 255) / 256, 256>>>(ew);

    for (int i = 0; i < NL; i++) {
        if (i == 0)
            node_gemm<1,0,1><<<ng_grid, 256, NG_SMEM>>>(Wi_in, bi_in, batch);
        else
            node_gemm<1,0,0><<<ng_grid, 256, NG_SMEM>>>(Wi_in + i * CH * CH, bi_in + i * CH, batch);
        edge_kernel<<<e_grid, 128, EDGE_SMEM>>>(ea, eidx, eidx + NE,
                                                We1 + i * FE * CH, be1 + i * CH,
                                                We2 + i * CH * CH, be2 + i * CH);
        if (i < NL - 1)
            node_gemm<2,0,0><<<ng_grid, 256, NG_SMEM>>>(Wi_out + i * CH * CH, bi_out + i * CH, batch);
        else
            node_gemm<2,1,0><<<ng_grid, 256, NG_SMEM>>>(Wi_out + i * CH * CH, bi_out + i * CH, batch);
    }

    readout_kernel<<<NGR, 32>>>(W_r1, b_r1, W_r2, b_r2, out);
}